// round 2
// baseline (speedup 1.0000x reference)
#include <cuda_runtime.h>
#include <cstdint>

// Problem constants (fixed by setup_inputs)
#define TT 32     // simulation length
#define LL 4      // number of cores
#define BB 128    // batch
#define HH 1024   // neurons/axons per core

// Ping-pong spike bitmask buffers: bit t of U[b*HH+a] = spike of (b,a) at cycle t.
__device__ unsigned g_bitsA[BB * HH];
__device__ unsigned g_bitsB[BB * HH];

// ---------------------------------------------------------------------------
// Spike encoding: bit-exact fp32 mirror of to_uniform_spikes.
//   N        = round(x*32)                      (rintf = round-half-even, = jnp.round)
//   spacing  = 32 / float(N)                    (single f32 divide, = reference)
//   q        = floor(c / spacing)               (f32 divide + floor)
//   r        = fmodf(c, spacing)                (EXACT IEEE remainder = lax.rem;
//                                                both operands >= 0 so jnp.mod's
//                                                sign adjustment is a no-op)
//   fire     = (0<N<32) & (q < N) & (floor(r)==0)
//   N==32 -> fire every cycle.
// ---------------------------------------------------------------------------
__global__ void encode_kernel(const float* __restrict__ x, unsigned* __restrict__ U)
{
    int idx = blockIdx.x * blockDim.x + threadIdx.x;
    if (idx >= BB * HH) return;
    float xv = x[idx];
    float Nf = rintf(__fmul_rn(xv, 32.0f));
    int   N  = (int)Nf;
    unsigned bits = 0u;
    if (N >= TT) {
        bits = 0xFFFFFFFFu;              // saturated: fire every cycle
    } else if (N > 0) {
        float spacing = __fdiv_rn(32.0f, (float)N);
        float fN = (float)N;
        #pragma unroll
        for (int t = 0; t < TT; ++t) {
            float c = (float)t;
            float q = floorf(__fdiv_rn(c, spacing));
            float r = fmodf(c, spacing);         // exact remainder (matches lax.rem)
            if (q < fN && floorf(r) == 0.0f) bits |= (1u << t);
        }
    }
    U[idx] = bits;
}

// ---------------------------------------------------------------------------
// One layer. CORRECTNESS-CRITICAL invariant: for every (b, n, t), z[t] is
// accumulated as a SINGLE fp32 accumulator over axons a in STRICT ASCENDING
// order (a0 tiles ascending, a within tile ascending). This reproduces
// Eigen/XLA-CPU's sequential-k FMA chain bit-exactly, because
// fma(0,w,acc)==acc and fma(1,w,acc)==acc+w (one rounding). Do not
// reassociate, split the accumulator, or reorder the a loop.
//
// Block = 256 threads = 8 b-rows x 32 n-cols. Warp <-> one b row, so the
// spike mask u is warp-uniform (uniform zero-skip) and sW reads are
// conflict-free across lanes.
// ---------------------------------------------------------------------------
template<int LAST>
__global__ void __launch_bounds__(256, 4) layer_kernel(
    const unsigned* __restrict__ Uin,
    const float*    __restrict__ W,        // (HH neurons, HH axons) row-major
    const float*    __restrict__ thresholds,
    int layer,
    unsigned* __restrict__ Uout,
    float*    __restrict__ out)
{
    __shared__ float    sW[32][33];   // [n_local][a_local], padded
    __shared__ unsigned sU[8][32];    // [b_local][a_local]

    const int tx     = threadIdx.x;
    const int lane_n = tx & 31;       // n within tile == lane id
    const int row    = tx >> 5;       // b within tile == warp id
    const int n      = blockIdx.x * 32 + lane_n;
    const int b      = blockIdx.y * 8  + row;
    const float thr  = thresholds[layer];

    float z[TT];
    #pragma unroll
    for (int t = 0; t < TT; ++t) z[t] = 0.0f;

    const int nbase = blockIdx.x * 32;
    const int bbase = blockIdx.y * 8;

    for (int a0 = 0; a0 < HH; a0 += 32) {
        // Stage W tile: 32 n x 32 a  (each thread loads 4, coalesced along a)
        #pragma unroll
        for (int i = 0; i < 4; ++i) {
            int lin = tx + i * 256;
            int wn  = lin >> 5;
            int wa  = lin & 31;
            sW[wn][wa] = W[(size_t)(nbase + wn) * HH + (a0 + wa)];
        }
        // Stage spike masks: 8 b x 32 a
        {
            int ub = tx >> 5;
            int ua = tx & 31;
            sU[ub][ua] = Uin[(bbase + ub) * HH + (a0 + ua)];
        }
        __syncthreads();

        #pragma unroll 4
        for (int a = 0; a < 32; ++a) {          // ascending a: required for exactness
            unsigned u = sU[row][a];            // warp-uniform
            if (u == 0u) continue;              // exact no-op (fma with s=0)
            float w = sW[lane_n][a];            // conflict-free
            #pragma unroll
            for (int t = 0; t < TT; ++t) {
                if (u & (1u << t)) z[t] += w;   // single-accumulator chain per t
            }
        }
        __syncthreads();
    }

    // LIF recurrence over 32 cycles, all in registers.
    // Matches reference scan: m = m + z_t (one f32 add); strict thr < m; subtract.
    float m = 0.0f;
    unsigned bits = 0u;
    #pragma unroll
    for (int t = 0; t < TT; ++t) {
        m = __fadd_rn(m, z[t]);
        if (thr < m) { m = __fsub_rn(m, thr); bits |= (1u << t); }
    }

    if (LAST) {
        out[b * HH + n] = (float)__popc(bits) * (1.0f / 32.0f);  // exact: count/32
    } else {
        Uout[b * HH + n] = bits;
    }
}

// ---------------------------------------------------------------------------
// Launch: encode -> 4 layer passes (ping-pong bitmask buffers).
// ---------------------------------------------------------------------------
extern "C" void kernel_launch(void* const* d_in, const int* in_sizes, int n_in,
                              void* d_out, int out_size)
{
    const float* x   = (const float*)d_in[0];                 // (128,1024)
    const float* Wts = (const float*)d_in[1];                 // (4,1024,1024)
    const float* thr = (const float*)d_in[2];                 // (4,)
    float* out = (float*)d_out;                               // (128,1024)

    static unsigned* pA = nullptr;
    static unsigned* pB = nullptr;
    if (!pA) {
        cudaGetSymbolAddress((void**)&pA, g_bitsA);
        cudaGetSymbolAddress((void**)&pB, g_bitsB);
    }

    encode_kernel<<<(BB * HH + 255) / 256, 256>>>(x, pA);

    dim3 grid(HH / 32, BB / 8);   // (32, 16) = 512 blocks
    const size_t Wstride = (size_t)HH * HH;

    layer_kernel<0><<<grid, 256>>>(pA, Wts + 0 * Wstride, thr, 0, pB, nullptr);
    layer_kernel<0><<<grid, 256>>>(pB, Wts + 1 * Wstride, thr, 1, pA, nullptr);
    layer_kernel<0><<<grid, 256>>>(pA, Wts + 2 * Wstride, thr, 2, pB, nullptr);
    layer_kernel<1><<<grid, 256>>>(pB, Wts + 3 * Wstride, thr, 3, nullptr, out);
}

// round 4
// speedup vs baseline: 1.1303x; 1.1303x over previous
#include <cuda_runtime.h>
#include <cstdint>

// Problem constants (fixed by setup_inputs)
#define TT 32     // simulation length
#define LL 4      // number of cores
#define BB 128    // batch
#define HH 1024   // neurons/axons per core

// Ping-pong spike bitmask buffers: bit t of U[b*HH+a] = spike of (b,a) at cycle t.
__device__ unsigned g_bitsA[BB * HH];
__device__ unsigned g_bitsB[BB * HH];

// ---------------------------------------------------------------------------
// Spike encoding: bit-exact fp32 mirror of to_uniform_spikes.
// (fmodf == lax.rem for nonneg operands; rintf == jnp.round.)
// ---------------------------------------------------------------------------
__global__ void encode_kernel(const float* __restrict__ x, unsigned* __restrict__ U)
{
    int idx = blockIdx.x * blockDim.x + threadIdx.x;
    if (idx >= BB * HH) return;
    float xv = x[idx];
    float Nf = rintf(__fmul_rn(xv, 32.0f));
    int   N  = (int)Nf;
    unsigned bits = 0u;
    if (N >= TT) {
        bits = 0xFFFFFFFFu;              // saturated: fire every cycle
    } else if (N > 0) {
        float spacing = __fdiv_rn(32.0f, (float)N);
        float fN = (float)N;
        #pragma unroll
        for (int t = 0; t < TT; ++t) {
            float c = (float)t;
            float q = floorf(__fdiv_rn(c, spacing));
            float r = fmodf(c, spacing);         // exact remainder (matches lax.rem)
            if (q < fN && floorf(r) == 0.0f) bits |= (1u << t);
        }
    }
    U[idx] = bits;
}

// ---------------------------------------------------------------------------
// One layer. CORRECTNESS-CRITICAL invariant: for every (b, n, t), z[t] is
// accumulated as a SINGLE fp32 accumulator over axons a in STRICT ASCENDING
// order. Do not reassociate, split the accumulator, or reorder the a loop.
//
// Each thread owns TWO neurons (n0 = nbase+lane, n1 = nbase+32+lane),
// which share the same spike mask u and its 32 bit tests — halving the
// ALU (test/branch) overhead per FADD. Weights for (n0,n1) are packed as a
// float2 in smem so one LDS.64 feeds both accumulator chains.
//
// Block = 128 threads = 4 b-rows x 32 lanes. Warp <-> one b row, so u is
// warp-uniform (uniform skip, branches never diverge).
// ---------------------------------------------------------------------------
template<int LAST>
__global__ void __launch_bounds__(128) layer_kernel(
    const unsigned* __restrict__ Uin,
    const float*    __restrict__ W,        // (HH neurons, HH axons) row-major
    const float*    __restrict__ thresholds,
    int layer,
    unsigned* __restrict__ Uout,
    float*    __restrict__ out)
{
    __shared__ float2   sW[32][33];   // [a_local][lane]: (.x = n0 w, .y = n1 w), padded
    __shared__ unsigned sU[4][32];    // [b_local][a_local]

    const int tx    = threadIdx.x;
    const int lane  = tx & 31;
    const int row   = tx >> 5;        // b within tile == warp id
    const int nbase = blockIdx.x * 64;
    const int bbase = blockIdx.y * 4;
    const int n0    = nbase + lane;
    const int n1    = nbase + 32 + lane;
    const int b     = bbase + row;
    const float thr = thresholds[layer];

    float z0[TT], z1[TT];
    #pragma unroll
    for (int t = 0; t < TT; ++t) { z0[t] = 0.0f; z1[t] = 0.0f; }

    for (int a0 = 0; a0 < HH; a0 += 32) {
        // Stage W tile: 64 n x 32 a. Coalesced global reads (32 consecutive
        // a per warp); rows 0..31 fill .x, rows 32..63 fill .y.
        #pragma unroll
        for (int i = 0; i < 16; ++i) {
            int lin = tx + i * 128;
            int wn  = lin >> 5;               // 0..63
            int wa  = lin & 31;
            float v = W[(size_t)(nbase + wn) * HH + (a0 + wa)];
            if (wn < 32) sW[wa][wn].x = v;
            else         sW[wa][wn - 32].y = v;
        }
        // Stage spike masks: 4 b x 32 a (one word per thread)
        sU[row][lane] = Uin[(bbase + row) * HH + (a0 + lane)];
        __syncthreads();

        #pragma unroll 4
        for (int a = 0; a < 32; ++a) {          // ascending a: required for exactness
            unsigned u = sU[row][a];            // warp-uniform
            if (u == 0u) continue;              // exact no-op (fma with s=0)
            float2 w = sW[a][lane];             // LDS.64, conflict-free
            #pragma unroll
            for (int t = 0; t < TT; ++t) {
                if (u & (1u << t)) {            // one test feeds two chains
                    z0[t] += w.x;
                    z1[t] += w.y;
                }
            }
        }
        __syncthreads();
    }

    // LIF recurrence over 32 cycles, all in registers.
    float m0 = 0.0f, m1 = 0.0f;
    unsigned bits0 = 0u, bits1 = 0u;
    #pragma unroll
    for (int t = 0; t < TT; ++t) {
        m0 = __fadd_rn(m0, z0[t]);
        if (thr < m0) { m0 = __fsub_rn(m0, thr); bits0 |= (1u << t); }
        m1 = __fadd_rn(m1, z1[t]);
        if (thr < m1) { m1 = __fsub_rn(m1, thr); bits1 |= (1u << t); }
    }

    if (LAST) {
        out[b * HH + n0] = (float)__popc(bits0) * (1.0f / 32.0f);
        out[b * HH + n1] = (float)__popc(bits1) * (1.0f / 32.0f);
    } else {
        Uout[b * HH + n0] = bits0;
        Uout[b * HH + n1] = bits1;
    }
}

// ---------------------------------------------------------------------------
// Launch: encode -> 4 layer passes (ping-pong bitmask buffers).
// ---------------------------------------------------------------------------
extern "C" void kernel_launch(void* const* d_in, const int* in_sizes, int n_in,
                              void* d_out, int out_size)
{
    const float* x   = (const float*)d_in[0];                 // (128,1024)
    const float* Wts = (const float*)d_in[1];                 // (4,1024,1024)
    const float* thr = (const float*)d_in[2];                 // (4,)
    float* out = (float*)d_out;                               // (128,1024)

    static unsigned* pA = nullptr;
    static unsigned* pB = nullptr;
    if (!pA) {
        cudaGetSymbolAddress((void**)&pA, g_bitsA);
        cudaGetSymbolAddress((void**)&pB, g_bitsB);
    }

    encode_kernel<<<(BB * HH + 255) / 256, 256>>>(x, pA);

    dim3 grid(HH / 64, BB / 4);   // (16, 32) = 512 blocks of 128 threads
    const size_t Wstride = (size_t)HH * HH;

    layer_kernel<0><<<grid, 128>>>(pA, Wts + 0 * Wstride, thr, 0, pB, nullptr);
    layer_kernel<0><<<grid, 128>>>(pB, Wts + 1 * Wstride, thr, 1, pA, nullptr);
    layer_kernel<0><<<grid, 128>>>(pA, Wts + 2 * Wstride, thr, 2, pB, nullptr);
    layer_kernel<1><<<grid, 128>>>(pB, Wts + 3 * Wstride, thr, 3, nullptr, out);
}